// round 3
// baseline (speedup 1.0000x reference)
#include <cuda_runtime.h>
#include <math.h>

// Fused masked-fill, 4 float4 per thread per tensor.
// Each 256-thread block covers 1024 consecutive float4 (= 16 rows of F=256).
// Prologue: stage rv in shared, warp-parallel rank -> per-row mask flags.
// Block 0 additionally writes the T-float mask output.
#define VPT 4   // float4 per thread per tensor

__global__ void __launch_bounds__(256)
fused_mask_kernel(const float4* __restrict__ a,
                  const float4* __restrict__ b,
                  const float4* __restrict__ c,
                  const float*  __restrict__ rv,
                  float4* __restrict__ oa,
                  float4* __restrict__ ob,
                  float4* __restrict__ oc,
                  float*  __restrict__ out_mask,
                  int vecN, int fvec, int T, int n_mask) {
    extern __shared__ float srv[];               // T floats of rv
    __shared__ unsigned char s_flag[VPT * 256 / 16]; // up to 64 rows (>=16+1 slack)

    const int tid = threadIdx.x;
    const int nthr = blockDim.x;

    for (int j = tid; j < T; j += nthr) srv[j] = rv[j];
    __syncthreads();

    const long long blockStart = (long long)blockIdx.x * nthr * VPT;

    // Row range covered by this block.
    const int r0 = (int)(blockStart / fvec);
    long long lastIdx = blockStart + (long long)nthr * VPT - 1;
    if (lastIdx >= vecN) lastIdx = vecN - 1;
    const int r1 = (lastIdx >= blockStart) ? (int)(lastIdx / fvec) : r0;
    const int nrows = r1 - r0 + 1;

    const int wid  = tid >> 5;
    const int lane = tid & 31;
    const int nwarps = nthr >> 5;

    // Warp-parallel rank per covered row.
    for (int w = wid; w < nrows; w += nwarps) {
        const int t = (r0 + w) % T;
        const float v = srv[t];
        int cnt = 0;
        for (int j = lane; j < T; j += 32) {
            const float u = srv[j];
            cnt += (u < v) || (u == v && j < t);
        }
        #pragma unroll
        for (int off = 16; off; off >>= 1)
            cnt += __shfl_down_sync(0xffffffffu, cnt, off);
        if (lane == 0) s_flag[w] = (cnt < n_mask) ? 1 : 0;
    }

    // Block 0 owns the T-float mask output.
    if (blockIdx.x == 0) {
        for (int t = tid; t < T; t += nthr) {
            const float v = srv[t];
            int cnt = 0;
            for (int j = 0; j < T; j++) {
                const float u = srv[j];
                cnt += (u < v) || (u == v && j < t);
            }
            out_mask[t] = (cnt < n_mask) ? 1.0f : 0.0f;
        }
    }
    __syncthreads();

    // Streaming masked copy: 4 float4 per tensor per thread.
    #pragma unroll
    for (int k = 0; k < VPT; k++) {
        const long long li = blockStart + (long long)k * nthr + tid;
        if (li >= vecN) break;
        const int i = (int)li;
        const int row = i / fvec;
        if (s_flag[row - r0]) {
            const float4 z = make_float4(0.f, 0.f, 0.f, 0.f);
            __stcs(&oa[i], z); __stcs(&ob[i], z); __stcs(&oc[i], z);
        } else {
            __stcs(&oa[i], __ldcs(&a[i]));
            __stcs(&ob[i], __ldcs(&b[i]));
            __stcs(&oc[i], __ldcs(&c[i]));
        }
    }
}

extern "C" void kernel_launch(void* const* d_in, const int* in_sizes, int n_in,
                              void* d_out, int out_size) {
    const float* x_tre = (const float*)d_in[0];
    const float* x_sea = (const float*)d_in[1];
    const float* x_res = (const float*)d_in[2];
    const float* rv    = (const float*)d_in[3];

    const int N = in_sizes[0];      // B*T*F elements per tensor
    const int T = in_sizes[3];

    int F = 256;
    if (N % T == 0 && (N / T) % 256 != 0) F = N / T;

    float* out = (float*)d_out;
    float* z_tre    = out;
    float* z_sea    = out + (size_t)N;
    float* z_res    = out + (size_t)2 * N;
    float* out_mask = out + (size_t)3 * N;

    const int n_mask = (int)ceil((double)T * 0.4);
    const int vecN = N / 4;
    const int fvec = F / 4;
    const int threads = 256;
    const int perBlock = threads * VPT;
    const int blocks = (vecN + perBlock - 1) / perBlock;
    const size_t shmem = (size_t)T * sizeof(float);

    fused_mask_kernel<<<blocks, threads, shmem>>>(
        (const float4*)x_tre, (const float4*)x_sea, (const float4*)x_res, rv,
        (float4*)z_tre, (float4*)z_sea, (float4*)z_res, out_mask,
        vecN, fvec, T, n_mask);
}

// round 4
// speedup vs baseline: 1.1383x; 1.1383x over previous
#include <cuda_runtime.h>
#include <math.h>

// Fused masked-fill. 1 float4 per thread per tensor (R1's optimal streaming
// shape). Mask flag computed PER-WARP with no shared memory and no
// __syncthreads: with F=256 (fvec=64) every 32-vec warp sits inside one
// time-row, so one rank computation per warp (16 LDG/lane of the 2KB rv
// array + one REDUX) produces a warp-uniform flag.
// mask[t] = rank(rv[t]) < n_mask (stable tie-break) == argsort(rv)[:n_mask].
__global__ void __launch_bounds__(256)
fused_mask_kernel(const float4* __restrict__ a,
                  const float4* __restrict__ b,
                  const float4* __restrict__ c,
                  const float*  __restrict__ rv,
                  float4* __restrict__ oa,
                  float4* __restrict__ ob,
                  float4* __restrict__ oc,
                  float*  __restrict__ out_mask,
                  int vecN, int fvec, int T, int n_mask) {
    const int tid  = threadIdx.x;
    const int lane = tid & 31;
    const int i    = blockIdx.x * 256 + tid;
    const int base = blockIdx.x * 256 + (tid & ~31);   // warp's first vec index

    if (base < vecN) {
        int last = base + 31; if (last >= vecN) last = vecN - 1;
        const int rowa = base / fvec;
        const int rowb = last / fvec;

        if (rowa == rowb) {
            // Fast path: warp-uniform row -> one warp-collective rank.
            const int t = rowa % T;
            const float v = __ldg(&rv[t]);
            int cnt = 0;
            #pragma unroll 4
            for (int j = lane; j < T; j += 32) {
                const float u = __ldg(&rv[j]);
                cnt += (u < v) || (u == v && j < t);
            }
            cnt = __reduce_add_sync(0xffffffffu, cnt);
            const bool masked = (cnt < n_mask);

            if (i < vecN) {
                if (masked) {
                    const float4 z = make_float4(0.f, 0.f, 0.f, 0.f);
                    oa[i] = z; ob[i] = z; oc[i] = z;
                } else {
                    oa[i] = a[i]; ob[i] = b[i]; oc[i] = c[i];
                }
            }
        } else if (i < vecN) {
            // General fallback: per-lane rank (divergent rows within warp).
            const int t = (i / fvec) % T;
            const float v = __ldg(&rv[t]);
            int cnt = 0;
            for (int j = 0; j < T; j++) {
                const float u = __ldg(&rv[j]);
                cnt += (u < v) || (u == v && j < t);
            }
            if (cnt < n_mask) {
                const float4 z = make_float4(0.f, 0.f, 0.f, 0.f);
                oa[i] = z; ob[i] = z; oc[i] = z;
            } else {
                oa[i] = a[i]; ob[i] = b[i]; oc[i] = c[i];
            }
        }
    }

    // Block 0 writes the T-float mask output (thread-serial ranks over a
    // shared-staged rv copy; ~1us, hidden under the other blocks' traffic).
    if (blockIdx.x == 0) {
        __shared__ float srv[2048];              // supports T <= 2048
        for (int j = tid; j < T; j += 256) srv[j] = rv[j];
        __syncthreads();
        for (int t = tid; t < T; t += 256) {
            const float v = srv[t];
            int cnt = 0;
            for (int j = 0; j < T; j++) {
                const float u = srv[j];
                cnt += (u < v) || (u == v && j < t);
            }
            out_mask[t] = (cnt < n_mask) ? 1.0f : 0.0f;
        }
    }
}

extern "C" void kernel_launch(void* const* d_in, const int* in_sizes, int n_in,
                              void* d_out, int out_size) {
    const float* x_tre = (const float*)d_in[0];
    const float* x_sea = (const float*)d_in[1];
    const float* x_res = (const float*)d_in[2];
    const float* rv    = (const float*)d_in[3];

    const int N = in_sizes[0];      // B*T*F elements per tensor
    const int T = in_sizes[3];

    int F = 256;
    if (N % T == 0 && (N / T) % 256 != 0) F = N / T;

    float* out = (float*)d_out;
    float* z_tre    = out;
    float* z_sea    = out + (size_t)N;
    float* z_res    = out + (size_t)2 * N;
    float* out_mask = out + (size_t)3 * N;

    const int n_mask = (int)ceil((double)T * 0.4);
    const int vecN = N / 4;
    const int fvec = F / 4;
    const int threads = 256;
    const int blocks = (vecN + threads - 1) / threads;

    fused_mask_kernel<<<blocks, threads>>>(
        (const float4*)x_tre, (const float4*)x_sea, (const float4*)x_res, rv,
        (float4*)z_tre, (float4*)z_sea, (float4*)z_res, out_mask,
        vecN, fvec, T, n_mask);
}